// round 10
// baseline (speedup 1.0000x reference)
#include <cuda_runtime.h>
#include <cuda_bf16.h>
#include <cstdint>

// SamplePDF: inverse-transform sampling, zero shared memory.
//   bins   : [N, 64]  sorted bin edges
//   weights: [N, 63]
//   u      : [N, 128]
//   out    : [N, 128]
//
// R10: software pipeline — each warp processes 4 consecutive rays and issues
// the NEXT ray's global loads before computing the current one, so DRAM sees
// a continuous request stream instead of one burst per warp-lifetime
// (profiles showed DRAM parked at 60% with no saturated pipe -> latency/
// burstiness bound). Compute core = R9: register-distributed CDF, h-index
// search (3 register levels + 3 shuffle probes), bf16x2-packed slope pair,
// intercept form sample = u*slope + c.

#define N_BINS 64
#define N_W    63
#define N_IMP  128
#define WARPS_PER_BLOCK 8
#define THREADS (WARPS_PER_BLOCK * 32)
#define RPW 4
#define FULL 0xffffffffu

struct RayIn {
    float  wa, wb;   // weights[2m], weights[2m+1] (+1e-5)
    float2 bv;       // bins[2m], bins[2m+1]
    float4 uv;       // u[lane*4 .. lane*4+3] of this lane's quarter
};

static __device__ __forceinline__
void load_ray(int ray, int lane,
              const float* __restrict__ weights,
              const float* __restrict__ bins,
              const float* __restrict__ u,
              RayIn& r)
{
    const float* wrow = weights + (long long)ray * N_W;
    const int l2 = lane * 2;
    r.wa = wrow[l2] + 1e-5f;
    r.wb = (l2 + 1 < N_W) ? wrow[l2 + 1] + 1e-5f : 0.0f;
    r.bv = ((const float2*)(bins + (long long)ray * N_BINS))[lane];
    r.uv = ((const float4*)(u    + (long long)ray * N_IMP ))[lane];
}

static __device__ __forceinline__
void process_ray(const RayIn& rin, int lane, float* __restrict__ orow)
{
    // ---- 32-wide inclusive scan of pair sums ------------------------------
    const float pairsum = rin.wa + rin.wb;
    float P = pairsum;
    #pragma unroll
    for (int d = 1; d < 32; d <<= 1) {
        float t = __shfl_up_sync(FULL, P, d);
        if (lane >= d) P += t;
    }
    const float total = __shfl_sync(FULL, P, 31);
    const float inv   = 1.0f / total;

    // distributed CDF in registers: evenv[m]=cdf[2m+2], oddv[m]=cdf[2m+1]
    const float evenv = P * inv;
    const float oddv  = (P - rin.wb) * inv;
    const float cdf2m = (P - pairsum) * inv;         // cdf[2m]

    // shifted copy for the level-4 probe: evsh[m] = evenv[m+1]
    const float evsh  = __shfl_down_sync(FULL, evenv, 1);

    // warp-uniform CDF values for the register search levels
    const float cdf8  = __shfl_sync(FULL, evenv,  3);
    const float cdf16 = __shfl_sync(FULL, evenv,  7);
    const float cdf24 = __shfl_sync(FULL, evenv, 11);
    const float cdf32 = __shfl_sync(FULL, evenv, 15);
    const float cdf40 = __shfl_sync(FULL, evenv, 19);
    const float cdf48 = __shfl_sync(FULL, evenv, 23);
    const float cdf56 = __shfl_sync(FULL, evenv, 27);

    // ---- per-interval slope + intercept (2 intervals/lane) ----------------
    float bnext = __shfl_down_sync(FULL, rin.bv.x, 1);   // b[2m+2]
    if (lane == 31) bnext = rin.bv.y;                    // slope[63] = 0
    const float pa = rin.wa * inv;
    const float pb = rin.wb * inv;
    const float da = (pa < 1e-5f) ? 1.0f : pa;
    const float db = (pb < 1e-5f) ? 1.0f : pb;
    const float sA = (rin.bv.y - rin.bv.x) / da;         // slope[2m]
    const float sB = (bnext    - rin.bv.y) / db;         // slope[2m+1]
    // round-to-bf16 (slopes >= 0, far below bf16 max)
    const uint32_t ra = (__float_as_uint(sA) + 0x8000u) & 0xffff0000u;
    const uint32_t rb = (__float_as_uint(sB) + 0x8000u) & 0xffff0000u;
    const uint32_t spk = rb | (ra >> 16);                // hi: odd, lo: even
    const float cav = fmaf(-cdf2m, __uint_as_float(ra), rin.bv.x);  // c[2m]
    const float cbv = fmaf(-oddv,  __uint_as_float(rb), rin.bv.y);  // c[2m+1]

    // ---- 4 samples per lane -----------------------------------------------
    const float uvs[4] = {rin.uv.x, rin.uv.y, rin.uv.z, rin.uv.w};
    float res[4];

    #pragma unroll
    for (int k = 0; k < 4; ++k) {
        const float uv = uvs[k];

        int h = 0;
        const bool c1 = cdf32 < uv;
        if (c1) h = 16;
        const float p2 = c1 ? cdf48 : cdf16;
        const bool  c2 = p2 < uv;
        if (c2) h += 8;
        const float p3 = c1 ? (c2 ? cdf56 : cdf40) : (c2 ? cdf24 : cdf8);
        if (p3 < uv) h += 4;

        const float q4 = __shfl_sync(FULL, evsh, h);   // cdf[2h+4]
        if (q4 < uv) h += 2;
        const float q2 = __shfl_sync(FULL, evenv, h);  // cdf[2h+2]
        if (q2 < uv) h += 1;
        const float q1 = __shfl_sync(FULL, oddv, h);   // cdf[2h+1]
        const bool odd = q1 < uv;                      // idx = 2h + odd

        const uint32_t sp = __shfl_sync(FULL, spk, h);
        const float cA = __shfl_sync(FULL, cav, h);
        const float cB = __shfl_sync(FULL, cbv, h);
        const float slope = __uint_as_float(odd ? (sp & 0xffff0000u)
                                                : (sp << 16));
        const float cval  = odd ? cB : cA;

        res[k] = fmaf(uv, slope, cval);
    }

    float4 o;
    o.x = res[0]; o.y = res[1]; o.z = res[2]; o.w = res[3];
    ((float4*)orow)[lane] = o;
}

__global__ __launch_bounds__(THREADS, 5)
void sample_pdf_kernel(const float* __restrict__ bins,
                       const float* __restrict__ weights,
                       const float* __restrict__ u,
                       float* __restrict__ out,
                       int n_rays)
{
    const int warp = threadIdx.x >> 5;
    const int lane = threadIdx.x & 31;
    const int ray0 = (blockIdx.x * WARPS_PER_BLOCK + warp) * RPW;
    if (ray0 >= n_rays) return;

    RayIn cur, nxt;
    load_ray(ray0, lane, weights, bins, u, cur);

    #pragma unroll
    for (int i = 0; i < RPW; ++i) {
        const int ray = ray0 + i;
        if (ray >= n_rays) break;
        const bool has_next = (i + 1 < RPW) && (ray + 1 < n_rays);
        if (has_next)
            load_ray(ray + 1, lane, weights, bins, u, nxt);   // prefetch
        process_ray(cur, lane, out + (long long)ray * N_IMP);
        if (has_next)
            cur = nxt;
    }
}

extern "C" void kernel_launch(void* const* d_in, const int* in_sizes, int n_in,
                              void* d_out, int out_size)
{
    const float* bins    = (const float*)d_in[0];
    const float* weights = (const float*)d_in[1];
    const float* u       = (const float*)d_in[2];
    float* out = (float*)d_out;

    const int n_rays = in_sizes[0] / N_BINS;
    const int rays_per_block = WARPS_PER_BLOCK * RPW;
    const int grid = (n_rays + rays_per_block - 1) / rays_per_block;
    sample_pdf_kernel<<<grid, THREADS>>>(bins, weights, u, out, n_rays);
}

// round 11
// speedup vs baseline: 1.0379x; 1.0379x over previous
#include <cuda_runtime.h>
#include <cuda_bf16.h>
#include <cstdint>

// SamplePDF: inverse-transform sampling, one warp per ray, zero shared memory.
//   bins   : [N, 64]  sorted bin edges
//   weights: [N, 63]
//   u      : [N, 128]
//   out    : [N, 128]
//
// R11: R9 compute core (register-distributed CDF, h-index search with 3
// register levels + 3 shuffle probes, bf16x2-packed slope pair, intercept
// form sample = u*slope + c) + STREAMING cache hints. Kernel time has been
// pinned at 77.6us across instruction-count/occupancy variants == the exact
// bytes floor (402MB @ 5.2TB/s), so the only lever left is raising achieved
// bandwidth: __ldcs on bins/u and __stcs on out (single-use streams, evict
// first); weights keep default policy (252B rows straddle lines -> adjacent
// rays reuse L2 lines).

#define N_BINS 64
#define N_W    63
#define N_IMP  128
#define WARPS_PER_BLOCK 8
#define THREADS (WARPS_PER_BLOCK * 32)
#define FULL 0xffffffffu

__global__ __launch_bounds__(THREADS, 6)
void sample_pdf_kernel(const float* __restrict__ bins,
                       const float* __restrict__ weights,
                       const float* __restrict__ u,
                       float* __restrict__ out,
                       int n_rays)
{
    const int warp = threadIdx.x >> 5;
    const int lane = threadIdx.x & 31;
    const int ray  = blockIdx.x * WARPS_PER_BLOCK + warp;
    if (ray >= n_rays) return;

    // ---- global loads up front (coalesced / vectorized, streaming) --------
    const float* wrow = weights + (long long)ray * N_W;
    const int l2 = lane * 2;
    const float wa = wrow[l2] + 1e-5f;                             // w[2m]
    const float wb = (l2 + 1 < N_W) ? wrow[l2 + 1] + 1e-5f : 0.0f; // w[2m+1]
    const float2 bv  = __ldcs((const float2*)(bins + (long long)ray * N_BINS) + lane);
    const float4 uv4 = __ldcs((const float4*)(u    + (long long)ray * N_IMP ) + lane);

    // ---- 32-wide inclusive scan of pair sums ------------------------------
    const float pairsum = wa + wb;
    float P = pairsum;
    #pragma unroll
    for (int d = 1; d < 32; d <<= 1) {
        float t = __shfl_up_sync(FULL, P, d);
        if (lane >= d) P += t;
    }
    const float total = __shfl_sync(FULL, P, 31);
    const float inv   = 1.0f / total;

    // distributed CDF in registers: evenv[m]=cdf[2m+2], oddv[m]=cdf[2m+1]
    const float evenv = P * inv;
    const float oddv  = (P - wb) * inv;
    const float cdf2m = (P - pairsum) * inv;        // cdf[2m] (exclusive)

    // shifted copy for the level-4 probe: evsh[m] = evenv[m+1]
    const float evsh  = __shfl_down_sync(FULL, evenv, 1);

    // warp-uniform CDF values for the register search levels
    const float cdf8  = __shfl_sync(FULL, evenv,  3);
    const float cdf16 = __shfl_sync(FULL, evenv,  7);
    const float cdf24 = __shfl_sync(FULL, evenv, 11);
    const float cdf32 = __shfl_sync(FULL, evenv, 15);
    const float cdf40 = __shfl_sync(FULL, evenv, 19);
    const float cdf48 = __shfl_sync(FULL, evenv, 23);
    const float cdf56 = __shfl_sync(FULL, evenv, 27);

    // ---- per-interval slope + intercept precompute (2 intervals/lane) -----
    // denom_i = pdf_i, clamped to 1 if < 1e-5 (exactly the reference rule).
    // slope_i = (b[i+1]-b[i]) / denom_i, rounded to bf16; intercept
    // c_i = b_i - cdf[i]*slope_bf16_i uses the ROUNDED slope so the line
    // passes exactly through (cdf[i], b[i]).
    float bnext = __shfl_down_sync(FULL, bv.x, 1);   // b[2m+2]
    if (lane == 31) bnext = bv.y;                    // width[63]=0 -> slope 0
    const float pa = wa * inv;
    const float pb = wb * inv;
    const float da = (pa < 1e-5f) ? 1.0f : pa;
    const float db = (pb < 1e-5f) ? 1.0f : pb;
    const float sA = (bv.y  - bv.x) / da;            // slope[2m]   (>= 0)
    const float sB = (bnext - bv.y) / db;            // slope[2m+1] (>= 0)
    // round-to-bf16 (round-half-up; slopes are nonnegative, << bf16 max)
    const uint32_t ra = (__float_as_uint(sA) + 0x8000u) & 0xffff0000u;
    const uint32_t rb = (__float_as_uint(sB) + 0x8000u) & 0xffff0000u;
    const float sAr = __uint_as_float(ra);
    const float sBr = __uint_as_float(rb);
    const uint32_t spk = rb | (ra >> 16);            // hi: slope_odd, lo: slope_even
    const float cav = fmaf(-cdf2m, sAr, bv.x);       // c[2m]
    const float cbv = fmaf(-oddv,  sBr, bv.y);       // c[2m+1]

    // ---- 4 samples per lane -----------------------------------------------
    float res[4];
    const float uvs[4] = {uv4.x, uv4.y, uv4.z, uv4.w};

    #pragma unroll
    for (int k = 0; k < 4; ++k) {
        const float uv = uvs[k];

        // register tree: largest h with cdf[2h] < uv, coarse to stride 4
        int h = 0;
        const bool c1 = cdf32 < uv;
        if (c1) h = 16;
        const float p2 = c1 ? cdf48 : cdf16;
        const bool  c2 = p2 < uv;
        if (c2) h += 8;
        const float p3 = c1 ? (c2 ? cdf56 : cdf40) : (c2 ? cdf24 : cdf8);
        if (p3 < uv) h += 4;

        // shuffle probes
        const float q4 = __shfl_sync(FULL, evsh, h);   // cdf[2h+4]
        if (q4 < uv) h += 2;
        const float q2 = __shfl_sync(FULL, evenv, h);  // cdf[2h+2]
        if (q2 < uv) h += 1;
        const float q1 = __shfl_sync(FULL, oddv, h);   // cdf[2h+1]
        const bool odd = q1 < uv;                      // idx = 2h + odd

        // gather: packed slopes (1 shfl) + both intercepts (2 shfl)
        const uint32_t sp = __shfl_sync(FULL, spk, h);
        const float cA = __shfl_sync(FULL, cav, h);
        const float cB = __shfl_sync(FULL, cbv, h);
        const float slope = __uint_as_float(odd ? (sp & 0xffff0000u)
                                                : (sp << 16));
        const float cval  = odd ? cB : cA;

        res[k] = fmaf(uv, slope, cval);
    }

    float4 o;
    o.x = res[0]; o.y = res[1]; o.z = res[2]; o.w = res[3];
    __stcs(((float4*)(out + (long long)ray * N_IMP)) + lane, o);
}

extern "C" void kernel_launch(void* const* d_in, const int* in_sizes, int n_in,
                              void* d_out, int out_size)
{
    const float* bins    = (const float*)d_in[0];
    const float* weights = (const float*)d_in[1];
    const float* u       = (const float*)d_in[2];
    float* out = (float*)d_out;

    const int n_rays = in_sizes[0] / N_BINS;
    const int grid   = (n_rays + WARPS_PER_BLOCK - 1) / WARPS_PER_BLOCK;
    sample_pdf_kernel<<<grid, THREADS>>>(bins, weights, u, out, n_rays);
}

// round 12
// speedup vs baseline: 1.0802x; 1.0407x over previous
#include <cuda_runtime.h>
#include <cuda_bf16.h>
#include <cstdint>

// SamplePDF: inverse-transform sampling, one warp per ray, zero shared memory.
//   bins   : [N, 64]  sorted bin edges
//   weights: [N, 63]
//   u      : [N, 128]
//   out    : [N, 128]
//
// R12: R11 compute core (register-distributed CDF, h-index search with 3
// register levels + 3 shuffle probes, bf16x2-packed slope pair, intercept
// form sample = u*slope + c, streaming cache hints), launched as 128-thread
// blocks (4 warps) for finer CTA granularity / better wave balance. Kernel
// has been pinned at the ~5.3TB/s effective-bandwidth floor across all
// instruction-side variants; this tests the last launch-side knob.

#define N_BINS 64
#define N_W    63
#define N_IMP  128
#define WARPS_PER_BLOCK 4
#define THREADS (WARPS_PER_BLOCK * 32)
#define FULL 0xffffffffu

__global__ __launch_bounds__(THREADS)
void sample_pdf_kernel(const float* __restrict__ bins,
                       const float* __restrict__ weights,
                       const float* __restrict__ u,
                       float* __restrict__ out,
                       int n_rays)
{
    const int warp = threadIdx.x >> 5;
    const int lane = threadIdx.x & 31;
    const int ray  = blockIdx.x * WARPS_PER_BLOCK + warp;
    if (ray >= n_rays) return;

    // ---- global loads up front (coalesced / vectorized, streaming) --------
    const float* wrow = weights + (long long)ray * N_W;
    const int l2 = lane * 2;
    const float wa = wrow[l2] + 1e-5f;                             // w[2m]
    const float wb = (l2 + 1 < N_W) ? wrow[l2 + 1] + 1e-5f : 0.0f; // w[2m+1]
    const float2 bv  = __ldcs((const float2*)(bins + (long long)ray * N_BINS) + lane);
    const float4 uv4 = __ldcs((const float4*)(u    + (long long)ray * N_IMP ) + lane);

    // ---- 32-wide inclusive scan of pair sums ------------------------------
    const float pairsum = wa + wb;
    float P = pairsum;
    #pragma unroll
    for (int d = 1; d < 32; d <<= 1) {
        float t = __shfl_up_sync(FULL, P, d);
        if (lane >= d) P += t;
    }
    const float total = __shfl_sync(FULL, P, 31);
    const float inv   = 1.0f / total;

    // distributed CDF in registers: evenv[m]=cdf[2m+2], oddv[m]=cdf[2m+1]
    const float evenv = P * inv;
    const float oddv  = (P - wb) * inv;
    const float cdf2m = (P - pairsum) * inv;        // cdf[2m] (exclusive)

    // shifted copy for the level-4 probe: evsh[m] = evenv[m+1]
    const float evsh  = __shfl_down_sync(FULL, evenv, 1);

    // warp-uniform CDF values for the register search levels
    const float cdf8  = __shfl_sync(FULL, evenv,  3);
    const float cdf16 = __shfl_sync(FULL, evenv,  7);
    const float cdf24 = __shfl_sync(FULL, evenv, 11);
    const float cdf32 = __shfl_sync(FULL, evenv, 15);
    const float cdf40 = __shfl_sync(FULL, evenv, 19);
    const float cdf48 = __shfl_sync(FULL, evenv, 23);
    const float cdf56 = __shfl_sync(FULL, evenv, 27);

    // ---- per-interval slope + intercept precompute (2 intervals/lane) -----
    // denom_i = pdf_i, clamped to 1 if < 1e-5 (exactly the reference rule).
    // slope_i = (b[i+1]-b[i]) / denom_i, rounded to bf16; intercept
    // c_i = b_i - cdf[i]*slope_bf16_i uses the ROUNDED slope so the line
    // passes exactly through (cdf[i], b[i]).
    float bnext = __shfl_down_sync(FULL, bv.x, 1);   // b[2m+2]
    if (lane == 31) bnext = bv.y;                    // width[63]=0 -> slope 0
    const float pa = wa * inv;
    const float pb = wb * inv;
    const float da = (pa < 1e-5f) ? 1.0f : pa;
    const float db = (pb < 1e-5f) ? 1.0f : pb;
    const float sA = (bv.y  - bv.x) / da;            // slope[2m]   (>= 0)
    const float sB = (bnext - bv.y) / db;            // slope[2m+1] (>= 0)
    // round-to-bf16 (round-half-up; slopes are nonnegative, << bf16 max)
    const uint32_t ra = (__float_as_uint(sA) + 0x8000u) & 0xffff0000u;
    const uint32_t rb = (__float_as_uint(sB) + 0x8000u) & 0xffff0000u;
    const float sAr = __uint_as_float(ra);
    const float sBr = __uint_as_float(rb);
    const uint32_t spk = rb | (ra >> 16);            // hi: slope_odd, lo: slope_even
    const float cav = fmaf(-cdf2m, sAr, bv.x);       // c[2m]
    const float cbv = fmaf(-oddv,  sBr, bv.y);       // c[2m+1]

    // ---- 4 samples per lane -----------------------------------------------
    float res[4];
    const float uvs[4] = {uv4.x, uv4.y, uv4.z, uv4.w};

    #pragma unroll
    for (int k = 0; k < 4; ++k) {
        const float uv = uvs[k];

        // register tree: largest h with cdf[2h] < uv, coarse to stride 4
        int h = 0;
        const bool c1 = cdf32 < uv;
        if (c1) h = 16;
        const float p2 = c1 ? cdf48 : cdf16;
        const bool  c2 = p2 < uv;
        if (c2) h += 8;
        const float p3 = c1 ? (c2 ? cdf56 : cdf40) : (c2 ? cdf24 : cdf8);
        if (p3 < uv) h += 4;

        // shuffle probes
        const float q4 = __shfl_sync(FULL, evsh, h);   // cdf[2h+4]
        if (q4 < uv) h += 2;
        const float q2 = __shfl_sync(FULL, evenv, h);  // cdf[2h+2]
        if (q2 < uv) h += 1;
        const float q1 = __shfl_sync(FULL, oddv, h);   // cdf[2h+1]
        const bool odd = q1 < uv;                      // idx = 2h + odd

        // gather: packed slopes (1 shfl) + both intercepts (2 shfl)
        const uint32_t sp = __shfl_sync(FULL, spk, h);
        const float cA = __shfl_sync(FULL, cav, h);
        const float cB = __shfl_sync(FULL, cbv, h);
        const float slope = __uint_as_float(odd ? (sp & 0xffff0000u)
                                                : (sp << 16));
        const float cval  = odd ? cB : cA;

        res[k] = fmaf(uv, slope, cval);
    }

    float4 o;
    o.x = res[0]; o.y = res[1]; o.z = res[2]; o.w = res[3];
    __stcs(((float4*)(out + (long long)ray * N_IMP)) + lane, o);
}

extern "C" void kernel_launch(void* const* d_in, const int* in_sizes, int n_in,
                              void* d_out, int out_size)
{
    const float* bins    = (const float*)d_in[0];
    const float* weights = (const float*)d_in[1];
    const float* u       = (const float*)d_in[2];
    float* out = (float*)d_out;

    const int n_rays = in_sizes[0] / N_BINS;
    const int grid   = (n_rays + WARPS_PER_BLOCK - 1) / WARPS_PER_BLOCK;
    sample_pdf_kernel<<<grid, THREADS>>>(bins, weights, u, out, n_rays);
}